// round 7
// baseline (speedup 1.0000x reference)
#include <cuda_runtime.h>
#include <math.h>

// ---------------------------------------------------------------------------
// ShowAttendTellCore: additive attention + single LSTM step (all fp32)
//   B=256, L=196, ATT_FEAT=2048, ATT_HID=512, RNN=512, INPUT_ENC=512
// ---------------------------------------------------------------------------

#define Bq 256
#define Lq 196
#define Aq 2048          // ATT_FEAT
#define Hq 512           // ATT_HID
#define Rq 512           // RNN_SIZE
#define Iq 512           // INPUT_ENC
#define MLq (Bq * Lq)    // 50176  (exactly 392 * 128)
#define KXq (Iq + Aq + Rq)  // 3072  (concat [xt | att_res | h0])
#define G4q (4 * Rq)        // 2048  (gates)

// -------------------- scratch (device globals; no allocs) ------------------
__device__ float g_att_h[Bq * Hq];           // [B, 512]
__device__ float g_spart[4 * MLq];           // score partials (4 n-tiles)
__device__ float g_weight[MLq];              // softmax weights [B, L]
__device__ float g_xcat[Bq * KXq];           // [B, 3072] = [xt | att_res | h0]
__device__ float g_Wcat[G4q * KXq];          // [2048, 3072] = [W_ih | W_hh]
__device__ float g_gpart[4 * Bq * G4q];      // gates split-K partials

// ---------------------------------------------------------------------------
// Big fused GEMM: for each row m (= b*196+l) and col n:
//   att[m,n] = sum_k att_feats[m,k] * W_ctx[n,k]
//   score_partial = sum_n W_alpha[n] * tanh(att[m,n] + b_ctx[n] + att_h[b,n])
// 128x128 tile, BK=8, 256 threads, 8x8 per thread. Exact sizes: no bounds.
// grid = (4 n-tiles, 392 m-tiles)
// ---------------------------------------------------------------------------
__global__ __launch_bounds__(256, 2)
void k_att_gemm_score(const float* __restrict__ Aft,
                      const float* __restrict__ Wctx,
                      const float* __restrict__ bctx,
                      const float* __restrict__ walpha)
{
    __shared__ float As[8][128];
    __shared__ float Bs[8][128];

    const int tid = threadIdx.x;
    const int m0 = blockIdx.y * 128;
    const int n0 = blockIdx.x * 128;

    // gmem load mapping: 128 rows x 8 k, one float4 per thread
    const int lrow = tid >> 1;
    const int lk   = (tid & 1) * 4;
    const float* Ap = Aft  + (size_t)(m0 + lrow) * 2048 + lk;
    const float* Bp = Wctx + (size_t)(n0 + lrow) * 2048 + lk;

    float4 aR = *(const float4*)Ap;
    float4 bR = *(const float4*)Bp;

    const int ty = tid >> 4;    // 0..15 -> rows ty*8
    const int tx = tid & 15;    // 0..15 -> cols tx*8

    float acc[8][8];
#pragma unroll
    for (int i = 0; i < 8; i++)
#pragma unroll
        for (int j = 0; j < 8; j++) acc[i][j] = 0.f;

#pragma unroll 1
    for (int kt = 0; kt < 2048 / 8; ++kt) {
        As[lk + 0][lrow] = aR.x; As[lk + 1][lrow] = aR.y;
        As[lk + 2][lrow] = aR.z; As[lk + 3][lrow] = aR.w;
        Bs[lk + 0][lrow] = bR.x; Bs[lk + 1][lrow] = bR.y;
        Bs[lk + 2][lrow] = bR.z; Bs[lk + 3][lrow] = bR.w;
        __syncthreads();

        if (kt < 2048 / 8 - 1) {
            aR = *(const float4*)(Ap + (size_t)(kt + 1) * 8);
            bR = *(const float4*)(Bp + (size_t)(kt + 1) * 8);
        }

#pragma unroll
        for (int kk = 0; kk < 8; kk++) {
            float4 a0 = *(const float4*)&As[kk][ty * 8];
            float4 a1 = *(const float4*)&As[kk][ty * 8 + 4];
            float4 b0 = *(const float4*)&Bs[kk][tx * 8];
            float4 b1 = *(const float4*)&Bs[kk][tx * 8 + 4];
            float af[8] = {a0.x, a0.y, a0.z, a0.w, a1.x, a1.y, a1.z, a1.w};
            float bf[8] = {b0.x, b0.y, b0.z, b0.w, b1.x, b1.y, b1.z, b1.w};
#pragma unroll
            for (int i = 0; i < 8; i++)
#pragma unroll
                for (int j = 0; j < 8; j++)
                    acc[i][j] += af[i] * bf[j];
        }
        __syncthreads();
    }

    // epilogue: tanh + W_alpha projection, reduce across the 16 column-threads
    float wv[8], bc[8];
#pragma unroll
    for (int j = 0; j < 8; j++) {
        int n = n0 + tx * 8 + j;
        wv[j] = walpha[n];
        bc[j] = bctx[n];
    }
#pragma unroll
    for (int i = 0; i < 8; i++) {
        int m = m0 + ty * 8 + i;
        int b = m / Lq;
        const float* ah = g_att_h + b * Hq + n0 + tx * 8;
        float s = 0.f;
#pragma unroll
        for (int j = 0; j < 8; j++) {
            float v = tanhf(acc[i][j] + bc[j] + ah[j]);
            s += v * wv[j];
        }
        // lanes within a 16-thread column group are lane%16; xor 8..1 stays inside
#pragma unroll
        for (int off = 8; off > 0; off >>= 1)
            s += __shfl_xor_sync(0xffffffffu, s, off);
        if (tx == 0) g_spart[blockIdx.x * MLq + m] = s;   // unique writer
    }
}

// ---------------------------------------------------------------------------
// Generic small SGEMM (NT): C[M,N] = A[M,K] * B[N,K]^T (+bias)
// 64x64 tile, BK=8, 128 threads, 8x4 per thread. M,N,K multiples of 64/8.
// grid = (N/64, M/64, splitk); if gridDim.z>1 writes partials (no bias).
// ---------------------------------------------------------------------------
__global__ __launch_bounds__(128)
void k_sgemm64(const float* __restrict__ A, int lda,
               const float* __restrict__ Bm, int ldb,
               float* __restrict__ C, int ldc,
               const float* __restrict__ bias,
               int kLen, int partStride)
{
    __shared__ float As[8][64];
    __shared__ float Bs[8][64];

    const int tid = threadIdx.x;
    const int n0 = blockIdx.x * 64;
    const int m0 = blockIdx.y * 64;
    const int kOff = blockIdx.z * kLen;

    const int lrow = tid >> 1;          // 0..63
    const int lk   = (tid & 1) * 4;
    const float* Ap = A  + (size_t)(m0 + lrow) * lda + kOff + lk;
    const float* Bp = Bm + (size_t)(n0 + lrow) * ldb + kOff + lk;

    float4 aR = *(const float4*)Ap;
    float4 bR = *(const float4*)Bp;

    const int ty = tid >> 4;   // 0..7  -> rows ty*8
    const int tx = tid & 15;   // 0..15 -> cols tx*4

    float acc[8][4];
#pragma unroll
    for (int i = 0; i < 8; i++)
#pragma unroll
        for (int j = 0; j < 4; j++) acc[i][j] = 0.f;

    const int nT = kLen / 8;
#pragma unroll 1
    for (int kt = 0; kt < nT; ++kt) {
        As[lk + 0][lrow] = aR.x; As[lk + 1][lrow] = aR.y;
        As[lk + 2][lrow] = aR.z; As[lk + 3][lrow] = aR.w;
        Bs[lk + 0][lrow] = bR.x; Bs[lk + 1][lrow] = bR.y;
        Bs[lk + 2][lrow] = bR.z; Bs[lk + 3][lrow] = bR.w;
        __syncthreads();

        if (kt + 1 < nT) {
            aR = *(const float4*)(Ap + (size_t)(kt + 1) * 8);
            bR = *(const float4*)(Bp + (size_t)(kt + 1) * 8);
        }

#pragma unroll
        for (int kk = 0; kk < 8; kk++) {
            float4 a0 = *(const float4*)&As[kk][ty * 8];
            float4 a1 = *(const float4*)&As[kk][ty * 8 + 4];
            float4 b0 = *(const float4*)&Bs[kk][tx * 4];
            float af[8] = {a0.x, a0.y, a0.z, a0.w, a1.x, a1.y, a1.z, a1.w};
            float bf[4] = {b0.x, b0.y, b0.z, b0.w};
#pragma unroll
            for (int i = 0; i < 8; i++)
#pragma unroll
                for (int j = 0; j < 4; j++)
                    acc[i][j] += af[i] * bf[j];
        }
        __syncthreads();
    }

    float* Cb = C + (size_t)blockIdx.z * partStride;
#pragma unroll
    for (int i = 0; i < 8; i++) {
        int m = m0 + ty * 8 + i;
#pragma unroll
        for (int j = 0; j < 4; j++) {
            int n = n0 + tx * 4 + j;
            float v = acc[i][j];
            if (bias) v += bias[n];
            Cb[(size_t)m * ldc + n] = v;
        }
    }
}

// ---------------------------------------------------------------------------
// Softmax over L per batch row. Sums the 4 n-tile score partials first.
// grid = B, block = 256.
// ---------------------------------------------------------------------------
__global__ void k_softmax()
{
    const int b = blockIdx.x;
    const int t = threadIdx.x;
    __shared__ float red[256];

    float myv = -1e30f;
    if (t < Lq) {
        int idx = b * Lq + t;
        myv = g_spart[idx] + g_spart[MLq + idx] +
              g_spart[2 * MLq + idx] + g_spart[3 * MLq + idx];
    }
    red[t] = myv;
    __syncthreads();
#pragma unroll
    for (int s = 128; s > 0; s >>= 1) {
        if (t < s) red[t] = fmaxf(red[t], red[t + s]);
        __syncthreads();
    }
    const float mx = red[0];
    __syncthreads();

    float e = (t < Lq) ? expf(myv - mx) : 0.f;
    red[t] = e;
    __syncthreads();
#pragma unroll
    for (int s = 128; s > 0; s >>= 1) {
        if (t < s) red[t] += red[t + s];
        __syncthreads();
    }
    const float sum = red[0];
    if (t < Lq) g_weight[b * Lq + t] = e / sum;
}

// ---------------------------------------------------------------------------
// att_res[b,a] = sum_l weight[b,l] * att_feats[b,l,a]; written straight into
// the xcat concat buffer at column Iq+a. grid = (A/256, B), block = 256.
// ---------------------------------------------------------------------------
__global__ void k_attres(const float* __restrict__ Aft)
{
    __shared__ float w[Lq];
    const int b = blockIdx.y;
    const int a = blockIdx.x * 256 + threadIdx.x;

    for (int l = threadIdx.x; l < Lq; l += 256)
        w[l] = g_weight[b * Lq + l];
    __syncthreads();

    const float* base = Aft + (size_t)b * Lq * Aq + a;
    float acc = 0.f;
#pragma unroll 4
    for (int l = 0; l < Lq; l++)
        acc += w[l] * base[(size_t)l * Aq];

    g_xcat[(size_t)b * KXq + Iq + a] = acc;
}

// pack xt and h0 into xcat. total = B*Iq + B*Rq = 262144, grid 1024x256 exact.
__global__ void k_pack_x(const float* __restrict__ xt, const float* __restrict__ h0)
{
    int idx = blockIdx.x * 256 + threadIdx.x;
    const int half = Bq * Iq;
    if (idx < half) {
        int b = idx / Iq, i = idx % Iq;
        g_xcat[(size_t)b * KXq + i] = xt[idx];
    } else {
        int j = idx - half;
        int b = j / Rq, r = j % Rq;
        g_xcat[(size_t)b * KXq + Iq + Aq + r] = h0[j];
    }
}

// pack [W_ih | W_hh] into Wcat [2048, 3072] (grid-stride)
__global__ void k_pack_w(const float* __restrict__ Wih, const float* __restrict__ Whh)
{
    const int total = G4q * KXq;
    for (int idx = blockIdx.x * blockDim.x + threadIdx.x; idx < total;
         idx += gridDim.x * blockDim.x) {
        int row = idx / KXq, c = idx % KXq;
        g_Wcat[idx] = (c < Iq + Aq) ? Wih[(size_t)row * (Iq + Aq) + c]
                                    : Whh[(size_t)row * Rq + (c - (Iq + Aq))];
    }
}

// LSTM elementwise: sums 4 gate split-K partials, applies gate nonlinearities,
// writes h to out[0:BR) and out[BR:2BR), c to out[2BR:3BR) per out_size.
__global__ void k_lstm(const float* __restrict__ c0, float* __restrict__ out, int out_size)
{
    const int idx = blockIdx.x * 256 + threadIdx.x;   // 0 .. B*R-1 (exact grid)
    const int b = idx >> 9;
    const int r = idx & 511;

    float gi = 0.f, gf = 0.f, gg = 0.f, go = 0.f;
#pragma unroll
    for (int p = 0; p < 4; p++) {
        const float* gp = g_gpart + (size_t)p * Bq * G4q + (size_t)b * G4q;
        gi += gp[r];
        gf += gp[Rq + r];
        gg += gp[2 * Rq + r];
        go += gp[3 * Rq + r];
    }
    float i_ = 1.f / (1.f + expf(-gi));
    float f_ = 1.f / (1.f + expf(-gf));
    float g_ = tanhf(gg);
    float o_ = 1.f / (1.f + expf(-go));
    float c = f_ * c0[idx] + i_ * g_;
    float h = o_ * tanhf(c);

    const int BR = Bq * Rq;
    out[idx] = h;
    if (out_size >= 2 * BR) out[BR + idx] = h;
    if (out_size >= 3 * BR) out[2 * BR + idx] = c;
}

// ---------------------------------------------------------------------------
extern "C" void kernel_launch(void* const* d_in, const int* in_sizes, int n_in,
                              void* d_out, int out_size)
{
    const float* xt     = (const float*)d_in[0];
    // d_in[1] = fc_feats: unused by the reference
    const float* attf   = (const float*)d_in[2];
    const float* h0     = (const float*)d_in[3];
    const float* c0     = (const float*)d_in[4];
    const float* Wctx   = (const float*)d_in[5];
    const float* bctx   = (const float*)d_in[6];
    const float* Wh2a   = (const float*)d_in[7];
    const float* bh2a   = (const float*)d_in[8];
    const float* Walpha = (const float*)d_in[9];
    // d_in[10] = b_alpha: softmax-invariant constant (and zero) -> skipped
    const float* Wih    = (const float*)d_in[11];
    const float* Whh    = (const float*)d_in[12];
    float* out = (float*)d_out;

    void* p;
    cudaGetSymbolAddress(&p, g_att_h); float* atth = (float*)p;
    cudaGetSymbolAddress(&p, g_xcat);  float* xcat = (float*)p;
    cudaGetSymbolAddress(&p, g_Wcat);  float* wcat = (float*)p;
    cudaGetSymbolAddress(&p, g_gpart); float* gpart = (float*)p;

    // independent packing work first
    k_pack_w<<<2048, 256>>>(Wih, Whh);
    k_pack_x<<<(Bq * Iq + Bq * Rq) / 256, 256>>>(xt, h0);

    // att_h = h0 @ W_h2a^T + b_h2a   [256, 512]
    k_sgemm64<<<dim3(Hq / 64, Bq / 64, 1), 128>>>(
        h0, Rq, Wh2a, Rq, atth, Hq, bh2a, Rq, 0);

    // fused big GEMM -> per-(b,l) score partials (4 n-tiles)
    k_att_gemm_score<<<dim3(Hq / 128, MLq / 128), 256>>>(attf, Wctx, bctx, Walpha);

    // softmax over L
    k_softmax<<<Bq, 256>>>();

    // att_res into xcat[:, 512:2560]
    k_attres<<<dim3(Aq / 256, Bq), 256>>>(attf);

    // gates = xcat @ Wcat^T, split-K = 4 (deterministic partials)
    k_sgemm64<<<dim3(G4q / 64, Bq / 64, 4), 128>>>(
        xcat, KXq, wcat, KXq, gpart, G4q, nullptr, KXq / 4, Bq * G4q);

    // LSTM cell + output writes
    k_lstm<<<(Bq * Rq) / 256, 256>>>(c0, out, out_size);
}

// round 9
// speedup vs baseline: 2.6895x; 2.6895x over previous
#include <cuda_runtime.h>
#include <cuda_bf16.h>
#include <cstdint>
#include <math.h>

// ---------------------------------------------------------------------------
// ShowAttendTellCore: additive attention + single LSTM step
//   B=256, L=196, ATT_FEAT=2048, ATT_HID=512, RNN=512, INPUT_ENC=512
// Big GEMM (50176x512x2048) via mma.sync tf32 (family-agnostic tensor path).
// ---------------------------------------------------------------------------

#define Bq 256
#define Lq 196
#define Aq 2048
#define Hq 512
#define Rq 512
#define Iq 512
#define MLq (Bq * Lq)        // 50176 = 392*128
#define KXq (Iq + Aq + Rq)   // 3072
#define G4q (4 * Rq)         // 2048

// -------------------- scratch (device globals; no allocs) ------------------
__device__ float g_att_h[Bq * Hq];
__device__ float g_spart[4 * MLq];           // score partials (4 n-tiles)
__device__ float g_weight[MLq];
__device__ float g_xcat[Bq * KXq];
__device__ float g_Wcat[G4q * KXq];
__device__ float g_gpart[4 * Bq * G4q];

// ======================= big GEMM via mma.sync tf32 ========================
// CTA tile 128x128, BK=32, 256 threads = 8 warps (2 m x 4 n), warp tile 64x32.
// smem per stage: A[128][36] + B[128][36] fp32 = 36864 B; 2 stages = 73728 B.
#define TSTRIDE 36
#define STAGE_FLOATS (2 * 128 * TSTRIDE)     // 9216
#define SMEM_MMA_BYTES (2 * STAGE_FLOATS * 4) // 73728

__device__ __forceinline__ void cp_async16(uint32_t saddr, const void* gaddr) {
    asm volatile("cp.async.cg.shared.global [%0], [%1], 16;"
                 :: "r"(saddr), "l"(gaddr));
}

__device__ __forceinline__ void mma_tf32(float* d, const float* a, const float* b) {
    asm volatile(
        "mma.sync.aligned.m16n8k8.row.col.f32.tf32.tf32.f32 "
        "{%0,%1,%2,%3}, {%4,%5,%6,%7}, {%8,%9}, {%0,%1,%2,%3};"
        : "+f"(d[0]), "+f"(d[1]), "+f"(d[2]), "+f"(d[3])
        : "r"(__float_as_uint(a[0])), "r"(__float_as_uint(a[1])),
          "r"(__float_as_uint(a[2])), "r"(__float_as_uint(a[3])),
          "r"(__float_as_uint(b[0])), "r"(__float_as_uint(b[1])));
}

__global__ __launch_bounds__(256, 1)
void k_att_mma(const float* __restrict__ Aft,
               const float* __restrict__ Wctx,
               const float* __restrict__ bctx,
               const float* __restrict__ walpha)
{
    extern __shared__ float sm[];
    const int tid = threadIdx.x;
    const int lane = tid & 31;
    const int wid = tid >> 5;
    const int wm = wid >> 2;        // 0..1 (m)
    const int wn = wid & 3;         // 0..3 (n)
    const int g = lane >> 2;        // groupID 0..7
    const int c = lane & 3;         // thread-in-group 0..3
    const int m0 = blockIdx.y * 128;
    const int n0 = blockIdx.x * 128;

    float acc[4][4][4];
#pragma unroll
    for (int mf = 0; mf < 4; mf++)
#pragma unroll
        for (int nf = 0; nf < 4; nf++)
#pragma unroll
            for (int r = 0; r < 4; r++) acc[mf][nf][r] = 0.f;

    // ---- async tile loader: 2048 x 16B chunks per stage, 8 per thread ----
    auto load_stage = [&](int kt, int s) {
        float* dstA = sm + s * STAGE_FLOATS;
        float* dstB = dstA + 128 * TSTRIDE;
        const int k0 = kt * 32;
#pragma unroll
        for (int i = 0; i < 4; i++) {
            int cid = i * 256 + tid;
            int row = cid >> 3;     // 0..127
            int kq  = cid & 7;      // 16B chunk within 32-float row
            cp_async16((uint32_t)__cvta_generic_to_shared(dstA + row * TSTRIDE + kq * 4),
                       Aft + (size_t)(m0 + row) * 2048 + k0 + kq * 4);
            cp_async16((uint32_t)__cvta_generic_to_shared(dstB + row * TSTRIDE + kq * 4),
                       Wctx + (size_t)(n0 + row) * 2048 + k0 + kq * 4);
        }
        asm volatile("cp.async.commit_group;" ::: "memory");
    };

    load_stage(0, 0);

#pragma unroll 1
    for (int kt = 0; kt < 2048 / 32; ++kt) {
        if (kt + 1 < 2048 / 32) {
            load_stage(kt + 1, (kt + 1) & 1);
            asm volatile("cp.async.wait_group 1;" ::: "memory");
        } else {
            asm volatile("cp.async.wait_group 0;" ::: "memory");
        }
        __syncthreads();

        const float* sA = sm + (kt & 1) * STAGE_FLOATS;
        const float* sB = sA + 128 * TSTRIDE;

#pragma unroll
        for (int ks = 0; ks < 4; ks++) {
            const int kb = ks * 8;
            float a[4][4], b[4][2];
#pragma unroll
            for (int mf = 0; mf < 4; mf++) {
                int r = wm * 64 + mf * 16 + g;
                a[mf][0] = sA[r * TSTRIDE + kb + c];
                a[mf][1] = sA[(r + 8) * TSTRIDE + kb + c];
                a[mf][2] = sA[r * TSTRIDE + kb + c + 4];
                a[mf][3] = sA[(r + 8) * TSTRIDE + kb + c + 4];
            }
#pragma unroll
            for (int nf = 0; nf < 4; nf++) {
                int col = wn * 32 + nf * 8 + g;
                b[nf][0] = sB[col * TSTRIDE + kb + c];
                b[nf][1] = sB[col * TSTRIDE + kb + c + 4];
            }
#pragma unroll
            for (int mf = 0; mf < 4; mf++)
#pragma unroll
                for (int nf = 0; nf < 4; nf++)
                    mma_tf32(acc[mf][nf], a[mf], b[nf]);
        }
        __syncthreads();
    }

    // ---- fused epilogue: tanh + W_alpha projection -> per-row partials ----
    // acc[mf][nf]: c0 at (row = wm*64+mf*16+g, col = wn*32+nf*8+2c), c1 col+1,
    //              c2/c3 at row+8.
    float* sred = sm;    // reuse smem: 128 rows x 4 warp_n floats
#pragma unroll
    for (int mf = 0; mf < 4; mf++) {
        int lr = wm * 64 + mf * 16 + g;
        int r0 = m0 + lr, r1 = r0 + 8;
        const float* ah0 = g_att_h + (size_t)(r0 / Lq) * Hq + n0;
        const float* ah1 = g_att_h + (size_t)(r1 / Lq) * Hq + n0;
        float rs0 = 0.f, rs1 = 0.f;
#pragma unroll
        for (int nf = 0; nf < 4; nf++) {
            int nl = wn * 32 + nf * 8 + 2 * c;
            float w0 = walpha[n0 + nl], w1 = walpha[n0 + nl + 1];
            float b0 = bctx[n0 + nl],  b1 = bctx[n0 + nl + 1];
            rs0 += w0 * tanhf(acc[mf][nf][0] + b0 + ah0[nl]);
            rs0 += w1 * tanhf(acc[mf][nf][1] + b1 + ah0[nl + 1]);
            rs1 += w0 * tanhf(acc[mf][nf][2] + b0 + ah1[nl]);
            rs1 += w1 * tanhf(acc[mf][nf][3] + b1 + ah1[nl + 1]);
        }
        rs0 += __shfl_xor_sync(0xffffffffu, rs0, 1);
        rs0 += __shfl_xor_sync(0xffffffffu, rs0, 2);
        rs1 += __shfl_xor_sync(0xffffffffu, rs1, 1);
        rs1 += __shfl_xor_sync(0xffffffffu, rs1, 2);
        if (c == 0) {
            sred[lr * 4 + wn] = rs0;
            sred[(lr + 8) * 4 + wn] = rs1;
        }
    }
    __syncthreads();
    if (tid < 128) {
        float s = sred[tid * 4 + 0] + sred[tid * 4 + 1] +
                  sred[tid * 4 + 2] + sred[tid * 4 + 3];
        g_spart[(size_t)blockIdx.x * MLq + m0 + tid] = s;
    }
}

// ======================= fp32 SGEMM (small mats) ===========================
__global__ __launch_bounds__(128)
void k_sgemm64(const float* __restrict__ A, int lda,
               const float* __restrict__ Bm, int ldb,
               float* __restrict__ C, int ldc,
               const float* __restrict__ bias,
               int kLen, int partStride)
{
    __shared__ float As[8][64];
    __shared__ float Bs[8][64];

    const int tid = threadIdx.x;
    const int n0 = blockIdx.x * 64;
    const int m0 = blockIdx.y * 64;
    const int kOff = blockIdx.z * kLen;

    const int lrow = tid >> 1;
    const int lk   = (tid & 1) * 4;
    const float* Ap = A  + (size_t)(m0 + lrow) * lda + kOff + lk;
    const float* Bp = Bm + (size_t)(n0 + lrow) * ldb + kOff + lk;

    float4 aR = *(const float4*)Ap;
    float4 bR = *(const float4*)Bp;

    const int ty = tid >> 4;
    const int tx = tid & 15;

    float acc[8][4];
#pragma unroll
    for (int i = 0; i < 8; i++)
#pragma unroll
        for (int j = 0; j < 4; j++) acc[i][j] = 0.f;

    const int nT = kLen / 8;
#pragma unroll 1
    for (int kt = 0; kt < nT; ++kt) {
        As[lk + 0][lrow] = aR.x; As[lk + 1][lrow] = aR.y;
        As[lk + 2][lrow] = aR.z; As[lk + 3][lrow] = aR.w;
        Bs[lk + 0][lrow] = bR.x; Bs[lk + 1][lrow] = bR.y;
        Bs[lk + 2][lrow] = bR.z; Bs[lk + 3][lrow] = bR.w;
        __syncthreads();

        if (kt + 1 < nT) {
            aR = *(const float4*)(Ap + (size_t)(kt + 1) * 8);
            bR = *(const float4*)(Bp + (size_t)(kt + 1) * 8);
        }

#pragma unroll
        for (int kk = 0; kk < 8; kk++) {
            float4 a0 = *(const float4*)&As[kk][ty * 8];
            float4 a1 = *(const float4*)&As[kk][ty * 8 + 4];
            float4 b0 = *(const float4*)&Bs[kk][tx * 4];
            float af[8] = {a0.x, a0.y, a0.z, a0.w, a1.x, a1.y, a1.z, a1.w};
            float bf[4] = {b0.x, b0.y, b0.z, b0.w};
#pragma unroll
            for (int i = 0; i < 8; i++)
#pragma unroll
                for (int j = 0; j < 4; j++)
                    acc[i][j] += af[i] * bf[j];
        }
        __syncthreads();
    }

    float* Cb = C + (size_t)blockIdx.z * partStride;
#pragma unroll
    for (int i = 0; i < 8; i++) {
        int m = m0 + ty * 8 + i;
#pragma unroll
        for (int j = 0; j < 4; j++) {
            int n = n0 + tx * 4 + j;
            float v = acc[i][j];
            if (bias) v += bias[n];
            Cb[(size_t)m * ldc + n] = v;
        }
    }
}

// =============================== softmax ===================================
__global__ void k_softmax()
{
    const int b = blockIdx.x;
    const int t = threadIdx.x;
    __shared__ float red[256];

    float myv = -1e30f;
    if (t < Lq) {
        int idx = b * Lq + t;
        myv = g_spart[idx] + g_spart[MLq + idx] +
              g_spart[2 * MLq + idx] + g_spart[3 * MLq + idx];
    }
    red[t] = myv;
    __syncthreads();
#pragma unroll
    for (int s = 128; s > 0; s >>= 1) {
        if (t < s) red[t] = fmaxf(red[t], red[t + s]);
        __syncthreads();
    }
    const float mx = red[0];
    __syncthreads();

    float e = (t < Lq) ? expf(myv - mx) : 0.f;
    red[t] = e;
    __syncthreads();
#pragma unroll
    for (int s = 128; s > 0; s >>= 1) {
        if (t < s) red[t] += red[t + s];
        __syncthreads();
    }
    const float sum = red[0];
    if (t < Lq) g_weight[b * Lq + t] = e / sum;
}

// =============================== att_res ===================================
__global__ void k_attres(const float* __restrict__ Aft)
{
    __shared__ float w[Lq];
    const int b = blockIdx.y;
    const int a = blockIdx.x * 256 + threadIdx.x;

    for (int l = threadIdx.x; l < Lq; l += 256)
        w[l] = g_weight[b * Lq + l];
    __syncthreads();

    const float* base = Aft + (size_t)b * Lq * Aq + a;
    float acc = 0.f;
#pragma unroll 4
    for (int l = 0; l < Lq; l++)
        acc += w[l] * base[(size_t)l * Aq];

    g_xcat[(size_t)b * KXq + Iq + a] = acc;
}

// ================================ packs ====================================
__global__ void k_pack_x(const float* __restrict__ xt, const float* __restrict__ h0)
{
    int idx = blockIdx.x * 256 + threadIdx.x;
    const int half = Bq * Iq;
    if (idx < half) {
        int b = idx / Iq, i = idx % Iq;
        g_xcat[(size_t)b * KXq + i] = xt[idx];
    } else {
        int j = idx - half;
        int b = j / Rq, r = j % Rq;
        g_xcat[(size_t)b * KXq + Iq + Aq + r] = h0[j];
    }
}

__global__ void k_pack_w(const float* __restrict__ Wih, const float* __restrict__ Whh)
{
    const int total = G4q * KXq;
    for (int idx = blockIdx.x * blockDim.x + threadIdx.x; idx < total;
         idx += gridDim.x * blockDim.x) {
        int row = idx / KXq, c = idx % KXq;
        g_Wcat[idx] = (c < Iq + Aq) ? Wih[(size_t)row * (Iq + Aq) + c]
                                    : Whh[(size_t)row * Rq + (c - (Iq + Aq))];
    }
}

// ================================= LSTM ====================================
__global__ void k_lstm(const float* __restrict__ c0, float* __restrict__ out, int out_size)
{
    const int idx = blockIdx.x * 256 + threadIdx.x;
    const int b = idx >> 9;
    const int r = idx & 511;

    float gi = 0.f, gf = 0.f, gg = 0.f, go = 0.f;
#pragma unroll
    for (int p = 0; p < 4; p++) {
        const float* gp = g_gpart + (size_t)p * Bq * G4q + (size_t)b * G4q;
        gi += gp[r];
        gf += gp[Rq + r];
        gg += gp[2 * Rq + r];
        go += gp[3 * Rq + r];
    }
    float i_ = 1.f / (1.f + expf(-gi));
    float f_ = 1.f / (1.f + expf(-gf));
    float g_ = tanhf(gg);
    float o_ = 1.f / (1.f + expf(-go));
    float c = f_ * c0[idx] + i_ * g_;
    float h = o_ * tanhf(c);

    const int BR = Bq * Rq;
    out[idx] = h;
    if (out_size >= 2 * BR) out[BR + idx] = h;
    if (out_size >= 3 * BR) out[2 * BR + idx] = c;
}

// ---------------------------------------------------------------------------
extern "C" void kernel_launch(void* const* d_in, const int* in_sizes, int n_in,
                              void* d_out, int out_size)
{
    const float* xt     = (const float*)d_in[0];
    const float* attf   = (const float*)d_in[2];
    const float* h0     = (const float*)d_in[3];
    const float* c0     = (const float*)d_in[4];
    const float* Wctx   = (const float*)d_in[5];
    const float* bctx   = (const float*)d_in[6];
    const float* Wh2a   = (const float*)d_in[7];
    const float* bh2a   = (const float*)d_in[8];
    const float* Walpha = (const float*)d_in[9];
    const float* Wih    = (const float*)d_in[11];
    const float* Whh    = (const float*)d_in[12];
    float* out = (float*)d_out;

    void* p;
    cudaGetSymbolAddress(&p, g_att_h); float* atth = (float*)p;
    cudaGetSymbolAddress(&p, g_xcat);  float* xcat = (float*)p;
    cudaGetSymbolAddress(&p, g_Wcat);  float* wcat = (float*)p;
    cudaGetSymbolAddress(&p, g_gpart); float* gpart = (float*)p;

    cudaFuncSetAttribute(k_att_mma, cudaFuncAttributeMaxDynamicSharedMemorySize,
                         SMEM_MMA_BYTES);

    k_pack_w<<<2048, 256>>>(Wih, Whh);
    k_pack_x<<<(Bq * Iq + Bq * Rq) / 256, 256>>>(xt, h0);

    // att_h = h0 @ W_h2a^T + b_h2a
    k_sgemm64<<<dim3(Hq / 64, Bq / 64, 1), 128>>>(
        h0, Rq, Wh2a, Rq, atth, Hq, bh2a, Rq, 0);

    // big fused GEMM (tf32 mma.sync) -> score partials (4 n-tiles)
    k_att_mma<<<dim3(Hq / 128, MLq / 128), 256, SMEM_MMA_BYTES>>>(
        attf, Wctx, bctx, Walpha);

    k_softmax<<<Bq, 256>>>();

    k_attres<<<dim3(Aq / 256, Bq), 256>>>(attf);

    k_sgemm64<<<dim3(G4q / 64, Bq / 64, 4), 128>>>(
        xcat, KXq, wcat, KXq, gpart, G4q, nullptr, KXq / 4, Bq * G4q);

    k_lstm<<<(Bq * Rq) / 256, 256>>>(c0, out, out_size);
}

// round 10
// speedup vs baseline: 3.0013x; 1.1159x over previous
#include <cuda_runtime.h>
#include <cuda_bf16.h>
#include <cstdint>
#include <math.h>

// ---------------------------------------------------------------------------
// ShowAttendTellCore: additive attention + single LSTM step
//   B=256, L=196, ATT_FEAT=2048, ATT_HID=512, RNN=512, INPUT_ENC=512
// All GEMMs on mma.sync tf32. Big GEMM fused with tanh+Walpha epilogue.
// ---------------------------------------------------------------------------

#define Bq 256
#define Lq 196
#define Aq 2048
#define Hq 512
#define Rq 512
#define Iq 512
#define MLq (Bq * Lq)        // 50176 = 392*128
#define KXq (Iq + Aq + Rq)   // 3072
#define G4q (4 * Rq)         // 2048

// -------------------- scratch (device globals; no allocs) ------------------
__device__ float g_att_h[Bq * Hq];
__device__ float g_spart[4 * MLq];           // score partials (4 n-tiles)
__device__ float g_weight[MLq];
__device__ float g_xcat[Bq * KXq];
__device__ float g_Wcat[G4q * KXq];
__device__ float g_gates[Bq * G4q];

// ========================= shared mma machinery ============================
// CTA tile 128x128, BK=32, 256 threads = 8 warps (2 m x 4 n), warp tile 64x32.
// smem per stage: A[128][36] + B[128][36] fp32 = 36864 B; 2 stages = 73728 B.
#define TSTRIDE 36
#define STAGE_FLOATS (2 * 128 * TSTRIDE)      // 9216
#define SMEM_MMA_BYTES (2 * STAGE_FLOATS * 4) // 73728

__device__ __forceinline__ void cp_async16(uint32_t saddr, const void* gaddr) {
    asm volatile("cp.async.cg.shared.global [%0], [%1], 16;"
                 :: "r"(saddr), "l"(gaddr));
}

__device__ __forceinline__ void mma_tf32(float* d, const float* a, const float* b) {
    asm volatile(
        "mma.sync.aligned.m16n8k8.row.col.f32.tf32.tf32.f32 "
        "{%0,%1,%2,%3}, {%4,%5,%6,%7}, {%8,%9}, {%0,%1,%2,%3};"
        : "+f"(d[0]), "+f"(d[1]), "+f"(d[2]), "+f"(d[3])
        : "r"(__float_as_uint(a[0])), "r"(__float_as_uint(a[1])),
          "r"(__float_as_uint(a[2])), "r"(__float_as_uint(a[3])),
          "r"(__float_as_uint(b[0])), "r"(__float_as_uint(b[1])));
}

// mainloop macro body shared by both kernels (A rows m0.., B rows n0..)
// Produces acc[4][4][4]. Requires sm (dynamic smem), tid/lane/warp decomp.
struct MmaCtx {
    int tid, lane, wid, wm, wn, g, c;
};

__device__ __forceinline__ void mma_mainloop(
    float acc[4][4][4], float* sm, const MmaCtx& X,
    const float* __restrict__ Ag, int lda, int m0,
    const float* __restrict__ Bg, int ldb, int n0, int nkt)
{
    auto load_stage = [&](int kt, int s) {
        float* dstA = sm + s * STAGE_FLOATS;
        float* dstB = dstA + 128 * TSTRIDE;
        const int k0 = kt * 32;
#pragma unroll
        for (int i = 0; i < 4; i++) {
            int cid = i * 256 + X.tid;
            int row = cid >> 3;
            int kq  = cid & 7;
            cp_async16((uint32_t)__cvta_generic_to_shared(dstA + row * TSTRIDE + kq * 4),
                       Ag + (size_t)(m0 + row) * lda + k0 + kq * 4);
            cp_async16((uint32_t)__cvta_generic_to_shared(dstB + row * TSTRIDE + kq * 4),
                       Bg + (size_t)(n0 + row) * ldb + k0 + kq * 4);
        }
        asm volatile("cp.async.commit_group;" ::: "memory");
    };

    load_stage(0, 0);

#pragma unroll 1
    for (int kt = 0; kt < nkt; ++kt) {
        if (kt + 1 < nkt) {
            load_stage(kt + 1, (kt + 1) & 1);
            asm volatile("cp.async.wait_group 1;" ::: "memory");
        } else {
            asm volatile("cp.async.wait_group 0;" ::: "memory");
        }
        __syncthreads();

        const float* sA = sm + (kt & 1) * STAGE_FLOATS;
        const float* sB = sA + 128 * TSTRIDE;

#pragma unroll
        for (int ks = 0; ks < 4; ks++) {
            const int kb = ks * 8;
            float a[4][4];
#pragma unroll
            for (int mf = 0; mf < 4; mf++) {
                int r = X.wm * 64 + mf * 16 + X.g;
                a[mf][0] = sA[r * TSTRIDE + kb + X.c];
                a[mf][1] = sA[(r + 8) * TSTRIDE + kb + X.c];
                a[mf][2] = sA[r * TSTRIDE + kb + X.c + 4];
                a[mf][3] = sA[(r + 8) * TSTRIDE + kb + X.c + 4];
            }
#pragma unroll
            for (int nf = 0; nf < 4; nf++) {
                int col = X.wn * 32 + nf * 8 + X.g;
                float b[2];
                b[0] = sB[col * TSTRIDE + kb + X.c];
                b[1] = sB[col * TSTRIDE + kb + X.c + 4];
#pragma unroll
                for (int mf = 0; mf < 4; mf++)
                    mma_tf32(acc[mf][nf], a[mf], b);
            }
        }
        __syncthreads();
    }
}

// ================= big fused GEMM: att + tanh + Walpha =====================
__global__ __launch_bounds__(256, 2)
void k_att_mma(const float* __restrict__ Aft,
               const float* __restrict__ Wctx,
               const float* __restrict__ bctx,
               const float* __restrict__ walpha)
{
    extern __shared__ float sm[];
    MmaCtx X;
    X.tid = threadIdx.x; X.lane = X.tid & 31; X.wid = X.tid >> 5;
    X.wm = X.wid >> 2; X.wn = X.wid & 3;
    X.g = X.lane >> 2; X.c = X.lane & 3;
    const int m0 = blockIdx.y * 128;
    const int n0 = blockIdx.x * 128;

    float acc[4][4][4];
#pragma unroll
    for (int mf = 0; mf < 4; mf++)
#pragma unroll
        for (int nf = 0; nf < 4; nf++)
#pragma unroll
            for (int r = 0; r < 4; r++) acc[mf][nf][r] = 0.f;

    mma_mainloop(acc, sm, X, Aft, 2048, m0, Wctx, 2048, n0, 2048 / 32);

    // fused epilogue: score partial per row
    float* sred = sm;   // reuse: 128 rows x 4 warp_n
#pragma unroll
    for (int mf = 0; mf < 4; mf++) {
        int lr = X.wm * 64 + mf * 16 + X.g;
        int r0 = m0 + lr, r1 = r0 + 8;
        const float* ah0 = g_att_h + (size_t)(r0 / Lq) * Hq + n0;
        const float* ah1 = g_att_h + (size_t)(r1 / Lq) * Hq + n0;
        float rs0 = 0.f, rs1 = 0.f;
#pragma unroll
        for (int nf = 0; nf < 4; nf++) {
            int nl = X.wn * 32 + nf * 8 + 2 * X.c;
            float w0 = walpha[n0 + nl], w1 = walpha[n0 + nl + 1];
            float b0 = bctx[n0 + nl],  b1 = bctx[n0 + nl + 1];
            rs0 += w0 * tanhf(acc[mf][nf][0] + b0 + ah0[nl]);
            rs0 += w1 * tanhf(acc[mf][nf][1] + b1 + ah0[nl + 1]);
            rs1 += w0 * tanhf(acc[mf][nf][2] + b0 + ah1[nl]);
            rs1 += w1 * tanhf(acc[mf][nf][3] + b1 + ah1[nl + 1]);
        }
        rs0 += __shfl_xor_sync(0xffffffffu, rs0, 1);
        rs0 += __shfl_xor_sync(0xffffffffu, rs0, 2);
        rs1 += __shfl_xor_sync(0xffffffffu, rs1, 1);
        rs1 += __shfl_xor_sync(0xffffffffu, rs1, 2);
        if (X.c == 0) {
            sred[lr * 4 + X.wn] = rs0;
            sred[(lr + 8) * 4 + X.wn] = rs1;
        }
    }
    __syncthreads();
    if (X.tid < 128) {
        float s = sred[X.tid * 4 + 0] + sred[X.tid * 4 + 1] +
                  sred[X.tid * 4 + 2] + sred[X.tid * 4 + 3];
        g_spart[(size_t)blockIdx.x * MLq + m0 + X.tid] = s;
    }
}

// ================ generic tf32 GEMM: C = A*B^T (+bias) =====================
__global__ __launch_bounds__(256, 2)
void k_gemm_tf32(const float* __restrict__ Ag, int lda,
                 const float* __restrict__ Bg, int ldb,
                 float* __restrict__ C, int ldc,
                 const float* __restrict__ bias, int nkt)
{
    extern __shared__ float sm[];
    MmaCtx X;
    X.tid = threadIdx.x; X.lane = X.tid & 31; X.wid = X.tid >> 5;
    X.wm = X.wid >> 2; X.wn = X.wid & 3;
    X.g = X.lane >> 2; X.c = X.lane & 3;
    const int m0 = blockIdx.y * 128;
    const int n0 = blockIdx.x * 128;

    float acc[4][4][4];
#pragma unroll
    for (int mf = 0; mf < 4; mf++)
#pragma unroll
        for (int nf = 0; nf < 4; nf++)
#pragma unroll
            for (int r = 0; r < 4; r++) acc[mf][nf][r] = 0.f;

    mma_mainloop(acc, sm, X, Ag, lda, m0, Bg, ldb, n0, nkt);

#pragma unroll
    for (int mf = 0; mf < 4; mf++) {
        int r0 = m0 + X.wm * 64 + mf * 16 + X.g;
#pragma unroll
        for (int nf = 0; nf < 4; nf++) {
            int nl = n0 + X.wn * 32 + nf * 8 + 2 * X.c;
            float b0 = bias ? bias[nl] : 0.f;
            float b1 = bias ? bias[nl + 1] : 0.f;
            *(float2*)&C[(size_t)r0 * ldc + nl] =
                make_float2(acc[mf][nf][0] + b0, acc[mf][nf][1] + b1);
            *(float2*)&C[(size_t)(r0 + 8) * ldc + nl] =
                make_float2(acc[mf][nf][2] + b0, acc[mf][nf][3] + b1);
        }
    }
}

// =============================== softmax ===================================
__global__ void k_softmax()
{
    const int b = blockIdx.x;
    const int t = threadIdx.x;
    __shared__ float red[256];

    float myv = -1e30f;
    if (t < Lq) {
        int idx = b * Lq + t;
        myv = g_spart[idx] + g_spart[MLq + idx] +
              g_spart[2 * MLq + idx] + g_spart[3 * MLq + idx];
    }
    red[t] = myv;
    __syncthreads();
#pragma unroll
    for (int s = 128; s > 0; s >>= 1) {
        if (t < s) red[t] = fmaxf(red[t], red[t + s]);
        __syncthreads();
    }
    const float mx = red[0];
    __syncthreads();

    float e = (t < Lq) ? expf(myv - mx) : 0.f;
    red[t] = e;
    __syncthreads();
#pragma unroll
    for (int s = 128; s > 0; s >>= 1) {
        if (t < s) red[t] += red[t + s];
        __syncthreads();
    }
    const float sum = red[0];
    if (t < Lq) g_weight[b * Lq + t] = e / sum;
}

// =============================== att_res ===================================
__global__ void k_attres(const float* __restrict__ Aft)
{
    __shared__ float w[Lq];
    const int b = blockIdx.y;
    const int a = blockIdx.x * 256 + threadIdx.x;

    for (int l = threadIdx.x; l < Lq; l += 256)
        w[l] = g_weight[b * Lq + l];
    __syncthreads();

    const float* base = Aft + (size_t)b * Lq * Aq + a;
    float acc = 0.f;
#pragma unroll 4
    for (int l = 0; l < Lq; l++)
        acc += w[l] * base[(size_t)l * Aq];

    g_xcat[(size_t)b * KXq + Iq + a] = acc;
}

// ================================ packs ====================================
__global__ void k_pack_x(const float* __restrict__ xt, const float* __restrict__ h0)
{
    int idx = blockIdx.x * 256 + threadIdx.x;
    const int half = Bq * Iq;
    if (idx < half) {
        int b = idx / Iq, i = idx % Iq;
        g_xcat[(size_t)b * KXq + i] = xt[idx];
    } else {
        int j = idx - half;
        int b = j / Rq, r = j % Rq;
        g_xcat[(size_t)b * KXq + Iq + Aq + r] = h0[j];
    }
}

__global__ void k_pack_w(const float* __restrict__ Wih, const float* __restrict__ Whh)
{
    const int total = G4q * KXq;
    for (int idx = blockIdx.x * blockDim.x + threadIdx.x; idx < total;
         idx += gridDim.x * blockDim.x) {
        int row = idx / KXq, c = idx % KXq;
        g_Wcat[idx] = (c < Iq + Aq) ? Wih[(size_t)row * (Iq + Aq) + c]
                                    : Whh[(size_t)row * Rq + (c - (Iq + Aq))];
    }
}

// ================================= LSTM ====================================
__global__ void k_lstm(const float* __restrict__ c0, float* __restrict__ out, int out_size)
{
    const int idx = blockIdx.x * 256 + threadIdx.x;
    const int b = idx >> 9;
    const int r = idx & 511;

    const float* gp = g_gates + (size_t)b * G4q;
    float gi = gp[r];
    float gf = gp[Rq + r];
    float gg = gp[2 * Rq + r];
    float go = gp[3 * Rq + r];

    float i_ = 1.f / (1.f + expf(-gi));
    float f_ = 1.f / (1.f + expf(-gf));
    float g_ = tanhf(gg);
    float o_ = 1.f / (1.f + expf(-go));
    float c = f_ * c0[idx] + i_ * g_;
    float h = o_ * tanhf(c);

    const int BR = Bq * Rq;
    out[idx] = h;
    if (out_size >= 2 * BR) out[BR + idx] = h;
    if (out_size >= 3 * BR) out[2 * BR + idx] = c;
}

// ---------------------------------------------------------------------------
extern "C" void kernel_launch(void* const* d_in, const int* in_sizes, int n_in,
                              void* d_out, int out_size)
{
    const float* xt     = (const float*)d_in[0];
    const float* attf   = (const float*)d_in[2];
    const float* h0     = (const float*)d_in[3];
    const float* c0     = (const float*)d_in[4];
    const float* Wctx   = (const float*)d_in[5];
    const float* bctx   = (const float*)d_in[6];
    const float* Wh2a   = (const float*)d_in[7];
    const float* bh2a   = (const float*)d_in[8];
    const float* Walpha = (const float*)d_in[9];
    const float* Wih    = (const float*)d_in[11];
    const float* Whh    = (const float*)d_in[12];
    float* out = (float*)d_out;

    void* p;
    cudaGetSymbolAddress(&p, g_att_h); float* atth = (float*)p;
    cudaGetSymbolAddress(&p, g_xcat);  float* xcat = (float*)p;
    cudaGetSymbolAddress(&p, g_Wcat);  float* wcat = (float*)p;
    cudaGetSymbolAddress(&p, g_gates); float* gates = (float*)p;

    cudaFuncSetAttribute(k_att_mma, cudaFuncAttributeMaxDynamicSharedMemorySize,
                         SMEM_MMA_BYTES);
    cudaFuncSetAttribute(k_gemm_tf32, cudaFuncAttributeMaxDynamicSharedMemorySize,
                         SMEM_MMA_BYTES);

    k_pack_w<<<2048, 256>>>(Wih, Whh);
    k_pack_x<<<(Bq * Iq + Bq * Rq) / 256, 256>>>(xt, h0);

    // att_h = h0 @ W_h2a^T + b_h2a   (tf32 mma; M=256,N=512,K=512)
    k_gemm_tf32<<<dim3(Hq / 128, Bq / 128), 256, SMEM_MMA_BYTES>>>(
        h0, Rq, Wh2a, Rq, atth, Hq, bh2a, Rq / 32);

    // big fused GEMM (tf32 mma) -> score partials (4 n-tiles)
    k_att_mma<<<dim3(Hq / 128, MLq / 128), 256, SMEM_MMA_BYTES>>>(
        attf, Wctx, bctx, Walpha);

    k_softmax<<<Bq, 256>>>();

    k_attres<<<dim3(Aq / 256, Bq), 256>>>(attf);

    // gates = xcat @ Wcat^T   (tf32 mma; M=256,N=2048,K=3072)
    k_gemm_tf32<<<dim3(G4q / 128, Bq / 128), 256, SMEM_MMA_BYTES>>>(
        xcat, KXq, wcat, KXq, gates, G4q, nullptr, KXq / 32);

    k_lstm<<<(Bq * Rq) / 256, 256>>>(c0, out, out_size);
}

// round 13
// speedup vs baseline: 3.4512x; 1.1499x over previous
#include <cuda_runtime.h>
#include <cuda_bf16.h>
#include <cstdint>
#include <math.h>

// ---------------------------------------------------------------------------
// ShowAttendTellCore: additive attention + single LSTM step
//   B=256, L=196, ATT_FEAT=2048, ATT_HID=512, RNN=512, INPUT_ENC=512
// All GEMMs on mma.sync tf32; 128-thread CTAs, warp tile 64x64 (2x2 warps)
// to halve smem crossbar traffic per MMA (R10 was LDS-bound).
// ---------------------------------------------------------------------------

#define Bq 256
#define Lq 196
#define Aq 2048
#define Hq 512
#define Rq 512
#define Iq 512
#define MLq (Bq * Lq)        // 50176 = 392*128
#define KXq (Iq + Aq + Rq)   // 3072
#define G4q (4 * Rq)         // 2048

// -------------------- scratch (device globals; no allocs) ------------------
__device__ float g_att_h[Bq * Hq];
__device__ float g_spart[4 * MLq];           // score partials (4 n-tiles)
__device__ float g_weight[MLq];
__device__ float g_xcat[Bq * KXq];
__device__ float g_Wcat[G4q * KXq];
__device__ float g_gpart[4 * Bq * G4q];      // gates split-K partials

// ========================= shared mma machinery ============================
// CTA tile 128x128, BK=32, 128 threads = 4 warps (2 m x 2 n), warp tile 64x64.
// smem per stage: A[128][36] + B[128][36] fp32 = 36864 B; 2 stages = 73728 B.
#define TSTRIDE 36
#define STAGE_FLOATS (2 * 128 * TSTRIDE)      // 9216
#define SMEM_MMA_BYTES (2 * STAGE_FLOATS * 4) // 73728

__device__ __forceinline__ void cp_async16(uint32_t saddr, const void* gaddr) {
    asm volatile("cp.async.cg.shared.global [%0], [%1], 16;"
                 :: "r"(saddr), "l"(gaddr));
}

__device__ __forceinline__ void mma_tf32(float* d, const float* a, const float* b) {
    asm volatile(
        "mma.sync.aligned.m16n8k8.row.col.f32.tf32.tf32.f32 "
        "{%0,%1,%2,%3}, {%4,%5,%6,%7}, {%8,%9}, {%0,%1,%2,%3};"
        : "+f"(d[0]), "+f"(d[1]), "+f"(d[2]), "+f"(d[3])
        : "r"(__float_as_uint(a[0])), "r"(__float_as_uint(a[1])),
          "r"(__float_as_uint(a[2])), "r"(__float_as_uint(a[3])),
          "r"(__float_as_uint(b[0])), "r"(__float_as_uint(b[1])));
}

struct MmaCtx {
    int tid, lane, wid, wm, wn, g, c;
};

// acc[mf<4][nf<8][4]; warp (wm,wn) in 2x2; warp tile 64x64.
__device__ __forceinline__ void mma_mainloop(
    float acc[4][8][4], float* sm, const MmaCtx& X,
    const float* __restrict__ Ag, int lda, int m0,
    const float* __restrict__ Bg, int ldb, int n0,
    int kOff, int nkt)
{
    auto load_stage = [&](int kt, int s) {
        float* dstA = sm + s * STAGE_FLOATS;
        float* dstB = dstA + 128 * TSTRIDE;
        const int k0 = kOff + kt * 32;
#pragma unroll
        for (int i = 0; i < 8; i++) {
            int cid = i * 128 + X.tid;
            int row = cid >> 3;
            int kq  = cid & 7;
            cp_async16((uint32_t)__cvta_generic_to_shared(dstA + row * TSTRIDE + kq * 4),
                       Ag + (size_t)(m0 + row) * lda + k0 + kq * 4);
            cp_async16((uint32_t)__cvta_generic_to_shared(dstB + row * TSTRIDE + kq * 4),
                       Bg + (size_t)(n0 + row) * ldb + k0 + kq * 4);
        }
        asm volatile("cp.async.commit_group;" ::: "memory");
    };

    load_stage(0, 0);

#pragma unroll 1
    for (int kt = 0; kt < nkt; ++kt) {
        if (kt + 1 < nkt) {
            load_stage(kt + 1, (kt + 1) & 1);
            asm volatile("cp.async.wait_group 1;" ::: "memory");
        } else {
            asm volatile("cp.async.wait_group 0;" ::: "memory");
        }
        __syncthreads();

        const float* sA = sm + (kt & 1) * STAGE_FLOATS;
        const float* sB = sA + 128 * TSTRIDE;

#pragma unroll
        for (int ks = 0; ks < 4; ks++) {
            const int kb = ks * 8;
            float a[4][4];
#pragma unroll
            for (int mf = 0; mf < 4; mf++) {
                int r = X.wm * 64 + mf * 16 + X.g;
                a[mf][0] = sA[r * TSTRIDE + kb + X.c];
                a[mf][1] = sA[(r + 8) * TSTRIDE + kb + X.c];
                a[mf][2] = sA[r * TSTRIDE + kb + X.c + 4];
                a[mf][3] = sA[(r + 8) * TSTRIDE + kb + X.c + 4];
            }
#pragma unroll
            for (int nf = 0; nf < 8; nf++) {
                int col = X.wn * 64 + nf * 8 + X.g;
                float b[2];
                b[0] = sB[col * TSTRIDE + kb + X.c];
                b[1] = sB[col * TSTRIDE + kb + X.c + 4];
#pragma unroll
                for (int mf = 0; mf < 4; mf++)
                    mma_tf32(acc[mf][nf], a[mf], b);
            }
        }
        __syncthreads();
    }
}

__device__ __forceinline__ MmaCtx make_ctx() {
    MmaCtx X;
    X.tid = threadIdx.x; X.lane = X.tid & 31; X.wid = X.tid >> 5;
    X.wm = X.wid >> 1; X.wn = X.wid & 1;
    X.g = X.lane >> 2; X.c = X.lane & 3;
    return X;
}

// ================= big fused GEMM: att + tanh + Walpha =====================
__global__ __launch_bounds__(128, 2)
void k_att_mma(const float* __restrict__ Aft,
               const float* __restrict__ Wctx,
               const float* __restrict__ bctx,
               const float* __restrict__ walpha)
{
    extern __shared__ float sm[];
    MmaCtx X = make_ctx();
    const int m0 = blockIdx.y * 128;
    const int n0 = blockIdx.x * 128;

    float acc[4][8][4];
#pragma unroll
    for (int mf = 0; mf < 4; mf++)
#pragma unroll
        for (int nf = 0; nf < 8; nf++)
#pragma unroll
            for (int r = 0; r < 4; r++) acc[mf][nf][r] = 0.f;

    mma_mainloop(acc, sm, X, Aft, 2048, m0, Wctx, 2048, n0, 0, 2048 / 32);

    // fused epilogue: score partial per row, reduce over 2 warp-n groups
    float* sred = sm;   // reuse: 128 rows x 2
#pragma unroll
    for (int mf = 0; mf < 4; mf++) {
        int lr = X.wm * 64 + mf * 16 + X.g;
        int r0 = m0 + lr, r1 = r0 + 8;
        const float* ah0 = g_att_h + (size_t)(r0 / Lq) * Hq + n0;
        const float* ah1 = g_att_h + (size_t)(r1 / Lq) * Hq + n0;
        float rs0 = 0.f, rs1 = 0.f;
#pragma unroll
        for (int nf = 0; nf < 8; nf++) {
            int nl = X.wn * 64 + nf * 8 + 2 * X.c;
            float w0 = walpha[n0 + nl], w1 = walpha[n0 + nl + 1];
            float b0 = bctx[n0 + nl],  b1 = bctx[n0 + nl + 1];
            rs0 += w0 * tanhf(acc[mf][nf][0] + b0 + ah0[nl]);
            rs0 += w1 * tanhf(acc[mf][nf][1] + b1 + ah0[nl + 1]);
            rs1 += w0 * tanhf(acc[mf][nf][2] + b0 + ah1[nl]);
            rs1 += w1 * tanhf(acc[mf][nf][3] + b1 + ah1[nl + 1]);
        }
        rs0 += __shfl_xor_sync(0xffffffffu, rs0, 1);
        rs0 += __shfl_xor_sync(0xffffffffu, rs0, 2);
        rs1 += __shfl_xor_sync(0xffffffffu, rs1, 1);
        rs1 += __shfl_xor_sync(0xffffffffu, rs1, 2);
        if (X.c == 0) {
            sred[lr * 2 + X.wn] = rs0;
            sred[(lr + 8) * 2 + X.wn] = rs1;
        }
    }
    __syncthreads();
    if (X.tid < 128) {
        float s = sred[X.tid * 2 + 0] + sred[X.tid * 2 + 1];
        g_spart[(size_t)blockIdx.x * MLq + m0 + X.tid] = s;
    }
}

// ================ generic tf32 GEMM: C = A*B^T (+bias) =====================
// grid.z = split-K; writes C + z*partStride, kOff = z*kLen, nkt = kLen/32.
__global__ __launch_bounds__(128, 2)
void k_gemm_tf32(const float* __restrict__ Ag, int lda,
                 const float* __restrict__ Bg, int ldb,
                 float* __restrict__ C, int ldc,
                 const float* __restrict__ bias,
                 int kLen, int partStride)
{
    extern __shared__ float sm[];
    MmaCtx X = make_ctx();
    const int m0 = blockIdx.y * 128;
    const int n0 = blockIdx.x * 128;

    float acc[4][8][4];
#pragma unroll
    for (int mf = 0; mf < 4; mf++)
#pragma unroll
        for (int nf = 0; nf < 8; nf++)
#pragma unroll
            for (int r = 0; r < 4; r++) acc[mf][nf][r] = 0.f;

    mma_mainloop(acc, sm, X, Ag, lda, m0, Bg, ldb, n0,
                 blockIdx.z * kLen, kLen / 32);

    float* Cb = C + (size_t)blockIdx.z * partStride;
#pragma unroll
    for (int mf = 0; mf < 4; mf++) {
        int r0 = m0 + X.wm * 64 + mf * 16 + X.g;
#pragma unroll
        for (int nf = 0; nf < 8; nf++) {
            int nl = n0 + X.wn * 64 + nf * 8 + 2 * X.c;
            float b0 = bias ? bias[nl] : 0.f;
            float b1 = bias ? bias[nl + 1] : 0.f;
            *(float2*)&Cb[(size_t)r0 * ldc + nl] =
                make_float2(acc[mf][nf][0] + b0, acc[mf][nf][1] + b1);
            *(float2*)&Cb[(size_t)(r0 + 8) * ldc + nl] =
                make_float2(acc[mf][nf][2] + b0, acc[mf][nf][3] + b1);
        }
    }
}

// =============================== softmax ===================================
__global__ void k_softmax()
{
    const int b = blockIdx.x;
    const int t = threadIdx.x;
    __shared__ float red[256];

    float myv = -1e30f;
    if (t < Lq) {
        int idx = b * Lq + t;
        myv = g_spart[idx] + g_spart[MLq + idx] +
              g_spart[2 * MLq + idx] + g_spart[3 * MLq + idx];
    }
    red[t] = myv;
    __syncthreads();
#pragma unroll
    for (int s = 128; s > 0; s >>= 1) {
        if (t < s) red[t] = fmaxf(red[t], red[t + s]);
        __syncthreads();
    }
    const float mx = red[0];
    __syncthreads();

    float e = (t < Lq) ? expf(myv - mx) : 0.f;
    red[t] = e;
    __syncthreads();
#pragma unroll
    for (int s = 128; s > 0; s >>= 1) {
        if (t < s) red[t] += red[t + s];
        __syncthreads();
    }
    const float sum = red[0];
    if (t < Lq) g_weight[b * Lq + t] = e / sum;
}

// =============================== att_res ===================================
__global__ void k_attres(const float* __restrict__ Aft)
{
    __shared__ float w[Lq];
    const int b = blockIdx.y;
    const int a = blockIdx.x * 256 + threadIdx.x;

    for (int l = threadIdx.x; l < Lq; l += 256)
        w[l] = g_weight[b * Lq + l];
    __syncthreads();

    const float* base = Aft + (size_t)b * Lq * Aq + a;
    float acc = 0.f;
#pragma unroll 4
    for (int l = 0; l < Lq; l++)
        acc += w[l] * base[(size_t)l * Aq];

    g_xcat[(size_t)b * KXq + Iq + a] = acc;
}

// ================================ packs ====================================
__global__ void k_pack_x(const float* __restrict__ xt, const float* __restrict__ h0)
{
    int idx = blockIdx.x * 256 + threadIdx.x;
    const int half = Bq * Iq;
    if (idx < half) {
        int b = idx / Iq, i = idx % Iq;
        g_xcat[(size_t)b * KXq + i] = xt[idx];
    } else {
        int j = idx - half;
        int b = j / Rq, r = j % Rq;
        g_xcat[(size_t)b * KXq + Iq + Aq + r] = h0[j];
    }
}

__global__ void k_pack_w(const float* __restrict__ Wih, const float* __restrict__ Whh)
{
    const int total = G4q * KXq;
    for (int idx = blockIdx.x * blockDim.x + threadIdx.x; idx < total;
         idx += gridDim.x * blockDim.x) {
        int row = idx / KXq, c = idx % KXq;
        g_Wcat[idx] = (c < Iq + Aq) ? Wih[(size_t)row * (Iq + Aq) + c]
                                    : Whh[(size_t)row * Rq + (c - (Iq + Aq))];
    }
}

// ================================= LSTM ====================================
__global__ void k_lstm(const float* __restrict__ c0, float* __restrict__ out, int out_size)
{
    const int idx = blockIdx.x * 256 + threadIdx.x;
    const int b = idx >> 9;
    const int r = idx & 511;

    float gi = 0.f, gf = 0.f, gg = 0.f, go = 0.f;
#pragma unroll
    for (int p = 0; p < 4; p++) {
        const float* gp = g_gpart + (size_t)p * Bq * G4q + (size_t)b * G4q;
        gi += gp[r];
        gf += gp[Rq + r];
        gg += gp[2 * Rq + r];
        go += gp[3 * Rq + r];
    }
    float i_ = 1.f / (1.f + expf(-gi));
    float f_ = 1.f / (1.f + expf(-gf));
    float g_ = tanhf(gg);
    float o_ = 1.f / (1.f + expf(-go));
    float c = f_ * c0[idx] + i_ * g_;
    float h = o_ * tanhf(c);

    const int BR = Bq * Rq;
    out[idx] = h;
    if (out_size >= 2 * BR) out[BR + idx] = h;
    if (out_size >= 3 * BR) out[2 * BR + idx] = c;
}

// ---------------------------------------------------------------------------
extern "C" void kernel_launch(void* const* d_in, const int* in_sizes, int n_in,
                              void* d_out, int out_size)
{
    const float* xt     = (const float*)d_in[0];
    const float* attf   = (const float*)d_in[2];
    const float* h0     = (const float*)d_in[3];
    const float* c0     = (const float*)d_in[4];
    const float* Wctx   = (const float*)d_in[5];
    const float* bctx   = (const float*)d_in[6];
    const float* Wh2a   = (const float*)d_in[7];
    const float* bh2a   = (const float*)d_in[8];
    const float* Walpha = (const float*)d_in[9];
    const float* Wih    = (const float*)d_in[11];
    const float* Whh    = (const float*)d_in[12];
    float* out = (float*)d_out;

    void* p;
    cudaGetSymbolAddress(&p, g_att_h); float* atth = (float*)p;
    cudaGetSymbolAddress(&p, g_xcat);  float* xcat = (float*)p;
    cudaGetSymbolAddress(&p, g_Wcat);  float* wcat = (float*)p;
    cudaGetSymbolAddress(&p, g_gpart); float* gpart = (float*)p;

    cudaFuncSetAttribute(k_att_mma, cudaFuncAttributeMaxDynamicSharedMemorySize,
                         SMEM_MMA_BYTES);
    cudaFuncSetAttribute(k_gemm_tf32, cudaFuncAttributeMaxDynamicSharedMemorySize,
                         SMEM_MMA_BYTES);

    k_pack_w<<<2048, 256>>>(Wih, Whh);
    k_pack_x<<<(Bq * Iq + Bq * Rq) / 256, 256>>>(xt, h0);

    // att_h = h0 @ W_h2a^T + b_h2a   (tf32 mma; M=256,N=512,K=512)
    k_gemm_tf32<<<dim3(Hq / 128, Bq / 128, 1), 128, SMEM_MMA_BYTES>>>(
        h0, Rq, Wh2a, Rq, atth, Hq, bh2a, Rq, 0);

    // big fused GEMM (tf32 mma) -> score partials (4 n-tiles)
    k_att_mma<<<dim3(Hq / 128, MLq / 128), 128, SMEM_MMA_BYTES>>>(
        attf, Wctx, bctx, Walpha);

    k_softmax<<<Bq, 256>>>();

    k_attres<<<dim3(Aq / 256, Bq), 256>>>(attf);

    // gates = xcat @ Wcat^T   (tf32 mma; M=256,N=2048,K=3072, split-K=4)
    k_gemm_tf32<<<dim3(G4q / 128, Bq / 128, 4), 128, SMEM_MMA_BYTES>>>(
        xcat, KXq, wcat, KXq, gpart, G4q, nullptr, KXq / 4, Bq * G4q);

    k_lstm<<<(Bq * Rq) / 256, 256>>>(c0, out, out_size);
}

// round 15
// speedup vs baseline: 3.4610x; 1.0029x over previous
#include <cuda_runtime.h>
#include <cuda_bf16.h>
#include <cstdint>
#include <math.h>

// ---------------------------------------------------------------------------
// ShowAttendTellCore: additive attention + single LSTM step
//   B=256, L=196, ATT_FEAT=2048, ATT_HID=512, RNN=512, INPUT_ENC=512
// All GEMMs on mma.sync tf32; 128-thread CTAs, warp tile 64x64 (2x2 warps).
// R14: 3-stage cp.async pipeline, ONE __syncthreads per k-chunk (was 2).
// ---------------------------------------------------------------------------

#define Bq 256
#define Lq 196
#define Aq 2048
#define Hq 512
#define Rq 512
#define Iq 512
#define MLq (Bq * Lq)        // 50176 = 392*128
#define KXq (Iq + Aq + Rq)   // 3072
#define G4q (4 * Rq)         // 2048

// -------------------- scratch (device globals; no allocs) ------------------
__device__ float g_att_h[Bq * Hq];
__device__ float g_spart[4 * MLq];           // score partials (4 n-tiles)
__device__ float g_weight[MLq];
__device__ float g_xcat[Bq * KXq];
__device__ float g_Wcat[G4q * KXq];
__device__ float g_gpart[4 * Bq * G4q];      // gates split-K partials

// ========================= shared mma machinery ============================
// CTA tile 128x128, BK=32, 128 threads = 4 warps (2 m x 2 n), warp tile 64x64.
// smem per stage: A[128][36] + B[128][36] fp32 = 36864 B; 3 stages = 110592 B.
#define TSTRIDE 36
#define STAGE_FLOATS (2 * 128 * TSTRIDE)      // 9216
#define NSTAGE 3
#define SMEM_MMA_BYTES (NSTAGE * STAGE_FLOATS * 4) // 110592

__device__ __forceinline__ void cp_async16(uint32_t saddr, const void* gaddr) {
    asm volatile("cp.async.cg.shared.global [%0], [%1], 16;"
                 :: "r"(saddr), "l"(gaddr));
}

__device__ __forceinline__ void mma_tf32(float* d, const float* a, const float* b) {
    asm volatile(
        "mma.sync.aligned.m16n8k8.row.col.f32.tf32.tf32.f32 "
        "{%0,%1,%2,%3}, {%4,%5,%6,%7}, {%8,%9}, {%0,%1,%2,%3};"
        : "+f"(d[0]), "+f"(d[1]), "+f"(d[2]), "+f"(d[3])
        : "r"(__float_as_uint(a[0])), "r"(__float_as_uint(a[1])),
          "r"(__float_as_uint(a[2])), "r"(__float_as_uint(a[3])),
          "r"(__float_as_uint(b[0])), "r"(__float_as_uint(b[1])));
}

struct MmaCtx {
    int tid, lane, wid, wm, wn, g, c;
};

// acc[mf<4][nf<8][4]; warp (wm,wn) in 2x2; warp tile 64x64.
// 3-stage pipeline: one barrier per kt. At top-of-kt barrier, all warps have
// finished compute(kt-1), so buffer (kt-1)%3 == (kt+2)%3 is free to refill.
__device__ __forceinline__ void mma_mainloop(
    float acc[4][8][4], float* sm, const MmaCtx& X,
    const float* __restrict__ Ag, int lda, int m0,
    const float* __restrict__ Bg, int ldb, int n0,
    int kOff, int nkt)
{
    auto load_stage = [&](int kt, int s) {
        float* dstA = sm + s * STAGE_FLOATS;
        float* dstB = dstA + 128 * TSTRIDE;
        const int k0 = kOff + kt * 32;
#pragma unroll
        for (int i = 0; i < 8; i++) {
            int cid = i * 128 + X.tid;
            int row = cid >> 3;
            int kq  = cid & 7;
            cp_async16((uint32_t)__cvta_generic_to_shared(dstA + row * TSTRIDE + kq * 4),
                       Ag + (size_t)(m0 + row) * lda + k0 + kq * 4);
            cp_async16((uint32_t)__cvta_generic_to_shared(dstB + row * TSTRIDE + kq * 4),
                       Bg + (size_t)(n0 + row) * ldb + k0 + kq * 4);
        }
        asm volatile("cp.async.commit_group;" ::: "memory");
    };

    load_stage(0, 0);
    if (nkt > 1) load_stage(1, 1);

    int ld = 2;                 // stage index for load of kt+2 == (kt+2)%3
    int cur = 0;                // stage index for compute == kt%3

#pragma unroll 1
    for (int kt = 0; kt < nkt; ++kt) {
        // wait for group kt (leave kt+1 pending if it exists)
        if (kt + 1 < nkt) {
            asm volatile("cp.async.wait_group 1;" ::: "memory");
        } else {
            asm volatile("cp.async.wait_group 0;" ::: "memory");
        }
        __syncthreads();        // group-kt data visible to all; kt-1 compute done

        if (kt + 2 < nkt) load_stage(kt + 2, ld);

        const float* sA = sm + cur * STAGE_FLOATS;
        const float* sB = sA + 128 * TSTRIDE;

#pragma unroll
        for (int ks = 0; ks < 4; ks++) {
            const int kb = ks * 8;
            float a[4][4];
#pragma unroll
            for (int mf = 0; mf < 4; mf++) {
                int r = X.wm * 64 + mf * 16 + X.g;
                a[mf][0] = sA[r * TSTRIDE + kb + X.c];
                a[mf][1] = sA[(r + 8) * TSTRIDE + kb + X.c];
                a[mf][2] = sA[r * TSTRIDE + kb + X.c + 4];
                a[mf][3] = sA[(r + 8) * TSTRIDE + kb + X.c + 4];
            }
#pragma unroll
            for (int nf = 0; nf < 8; nf++) {
                int col = X.wn * 64 + nf * 8 + X.g;
                float b[2];
                b[0] = sB[col * TSTRIDE + kb + X.c];
                b[1] = sB[col * TSTRIDE + kb + X.c + 4];
#pragma unroll
                for (int mf = 0; mf < 4; mf++)
                    mma_tf32(acc[mf][nf], a[mf], b);
            }
        }
        // rotate stage counters (no trailing barrier: next top barrier covers WAR)
        if (++ld == NSTAGE) ld = 0;
        if (++cur == NSTAGE) cur = 0;
    }
    __syncthreads();            // protect smem reuse (epilogue scratch)
}

__device__ __forceinline__ MmaCtx make_ctx() {
    MmaCtx X;
    X.tid = threadIdx.x; X.lane = X.tid & 31; X.wid = X.tid >> 5;
    X.wm = X.wid >> 1; X.wn = X.wid & 1;
    X.g = X.lane >> 2; X.c = X.lane & 3;
    return X;
}

// ================= big fused GEMM: att + tanh + Walpha =====================
__global__ __launch_bounds__(128, 2)
void k_att_mma(const float* __restrict__ Aft,
               const float* __restrict__ Wctx,
               const float* __restrict__ bctx,
               const float* __restrict__ walpha)
{
    extern __shared__ float sm[];
    MmaCtx X = make_ctx();
    const int m0 = blockIdx.y * 128;
    const int n0 = blockIdx.x * 128;

    float acc[4][8][4];
#pragma unroll
    for (int mf = 0; mf < 4; mf++)
#pragma unroll
        for (int nf = 0; nf < 8; nf++)
#pragma unroll
            for (int r = 0; r < 4; r++) acc[mf][nf][r] = 0.f;

    mma_mainloop(acc, sm, X, Aft, 2048, m0, Wctx, 2048, n0, 0, 2048 / 32);

    // fused epilogue: score partial per row, reduce over 2 warp-n groups
    float* sred = sm;   // reuse: 128 rows x 2
#pragma unroll
    for (int mf = 0; mf < 4; mf++) {
        int lr = X.wm * 64 + mf * 16 + X.g;
        int r0 = m0 + lr, r1 = r0 + 8;
        const float* ah0 = g_att_h + (size_t)(r0 / Lq) * Hq + n0;
        const float* ah1 = g_att_h + (size_t)(r1 / Lq) * Hq + n0;
        float rs0 = 0.f, rs1 = 0.f;
#pragma unroll
        for (int nf = 0; nf < 8; nf++) {
            int nl = X.wn * 64 + nf * 8 + 2 * X.c;
            float w0 = walpha[n0 + nl], w1 = walpha[n0 + nl + 1];
            float b0 = bctx[n0 + nl],  b1 = bctx[n0 + nl + 1];
            rs0 += w0 * tanhf(acc[mf][nf][0] + b0 + ah0[nl]);
            rs0 += w1 * tanhf(acc[mf][nf][1] + b1 + ah0[nl + 1]);
            rs1 += w0 * tanhf(acc[mf][nf][2] + b0 + ah1[nl]);
            rs1 += w1 * tanhf(acc[mf][nf][3] + b1 + ah1[nl + 1]);
        }
        rs0 += __shfl_xor_sync(0xffffffffu, rs0, 1);
        rs0 += __shfl_xor_sync(0xffffffffu, rs0, 2);
        rs1 += __shfl_xor_sync(0xffffffffu, rs1, 1);
        rs1 += __shfl_xor_sync(0xffffffffu, rs1, 2);
        if (X.c == 0) {
            sred[lr * 2 + X.wn] = rs0;
            sred[(lr + 8) * 2 + X.wn] = rs1;
        }
    }
    __syncthreads();
    if (X.tid < 128) {
        float s = sred[X.tid * 2 + 0] + sred[X.tid * 2 + 1];
        g_spart[(size_t)blockIdx.x * MLq + m0 + X.tid] = s;
    }
}

// ================ generic tf32 GEMM: C = A*B^T (+bias) =====================
// grid.z = split-K; writes C + z*partStride, kOff = z*kLen, nkt = kLen/32.
__global__ __launch_bounds__(128, 2)
void k_gemm_tf32(const float* __restrict__ Ag, int lda,
                 const float* __restrict__ Bg, int ldb,
                 float* __restrict__ C, int ldc,
                 const float* __restrict__ bias,
                 int kLen, int partStride)
{
    extern __shared__ float sm[];
    MmaCtx X = make_ctx();
    const int m0 = blockIdx.y * 128;
    const int n0 = blockIdx.x * 128;

    float acc[4][8][4];
#pragma unroll
    for (int mf = 0; mf < 4; mf++)
#pragma unroll
        for (int nf = 0; nf < 8; nf++)
#pragma unroll
            for (int r = 0; r < 4; r++) acc[mf][nf][r] = 0.f;

    mma_mainloop(acc, sm, X, Ag, lda, m0, Bg, ldb, n0,
                 blockIdx.z * kLen, kLen / 32);

    float* Cb = C + (size_t)blockIdx.z * partStride;
#pragma unroll
    for (int mf = 0; mf < 4; mf++) {
        int r0 = m0 + X.wm * 64 + mf * 16 + X.g;
#pragma unroll
        for (int nf = 0; nf < 8; nf++) {
            int nl = n0 + X.wn * 64 + nf * 8 + 2 * X.c;
            float b0 = bias ? bias[nl] : 0.f;
            float b1 = bias ? bias[nl + 1] : 0.f;
            *(float2*)&Cb[(size_t)r0 * ldc + nl] =
                make_float2(acc[mf][nf][0] + b0, acc[mf][nf][1] + b1);
            *(float2*)&Cb[(size_t)(r0 + 8) * ldc + nl] =
                make_float2(acc[mf][nf][2] + b0, acc[mf][nf][3] + b1);
        }
    }
}

// =============================== softmax ===================================
__global__ void k_softmax()
{
    const int b = blockIdx.x;
    const int t = threadIdx.x;
    __shared__ float red[256];

    float myv = -1e30f;
    if (t < Lq) {
        int idx = b * Lq + t;
        myv = g_spart[idx] + g_spart[MLq + idx] +
              g_spart[2 * MLq + idx] + g_spart[3 * MLq + idx];
    }
    red[t] = myv;
    __syncthreads();
#pragma unroll
    for (int s = 128; s > 0; s >>= 1) {
        if (t < s) red[t] = fmaxf(red[t], red[t + s]);
        __syncthreads();
    }
    const float mx = red[0];
    __syncthreads();

    float e = (t < Lq) ? expf(myv - mx) : 0.f;
    red[t] = e;
    __syncthreads();
#pragma unroll
    for (int s = 128; s > 0; s >>= 1) {
        if (t < s) red[t] += red[t + s];
        __syncthreads();
    }
    const float sum = red[0];
    if (t < Lq) g_weight[b * Lq + t] = e / sum;
}

// =============================== att_res ===================================
__global__ void k_attres(const float* __restrict__ Aft)
{
    __shared__ float w[Lq];
    const int b = blockIdx.y;
    const int a = blockIdx.x * 256 + threadIdx.x;

    for (int l = threadIdx.x; l < Lq; l += 256)
        w[l] = g_weight[b * Lq + l];
    __syncthreads();

    const float* base = Aft + (size_t)b * Lq * Aq + a;
    float acc = 0.f;
#pragma unroll 4
    for (int l = 0; l < Lq; l++)
        acc += w[l] * base[(size_t)l * Aq];

    g_xcat[(size_t)b * KXq + Iq + a] = acc;
}

// ================================ packs ====================================
__global__ void k_pack_x(const float* __restrict__ xt, const float* __restrict__ h0)
{
    int idx = blockIdx.x * 256 + threadIdx.x;
    const int half = Bq * Iq;
    if (idx < half) {
        int b = idx / Iq, i = idx % Iq;
        g_xcat[(size_t)b * KXq + i] = xt[idx];
    } else {
        int j = idx - half;
        int b = j / Rq, r = j % Rq;
        g_xcat[(size_t)b * KXq + Iq + Aq + r] = h0[j];
    }
}

__global__ void k_pack_w(const float* __restrict__ Wih, const float* __restrict__ Whh)
{
    const int total = G4q * KXq;
    for (int idx = blockIdx.x * blockDim.x + threadIdx.x; idx < total;
         idx += gridDim.x * blockDim.x) {
        int row = idx / KXq, c = idx % KXq;
        g_Wcat[idx] = (c < Iq + Aq) ? Wih[(size_t)row * (Iq + Aq) + c]
                                    : Whh[(size_t)row * Rq + (c - (Iq + Aq))];
    }
}

// ================================= LSTM ====================================
__global__ void k_lstm(const float* __restrict__ c0, float* __restrict__ out, int out_size)
{
    const int idx = blockIdx.x * 256 + threadIdx.x;
    const int b = idx >> 9;
    const int r = idx & 511;

    float gi = 0.f, gf = 0.f, gg = 0.f, go = 0.f;
#pragma unroll
    for (int p = 0; p < 4; p++) {
        const float* gp = g_gpart + (size_t)p * Bq * G4q + (size_t)b * G4q;
        gi += gp[r];
        gf += gp[Rq + r];
        gg += gp[2 * Rq + r];
        go += gp[3 * Rq + r];
    }
    float i_ = 1.f / (1.f + expf(-gi));
    float f_ = 1.f / (1.f + expf(-gf));
    float g_ = tanhf(gg);
    float o_ = 1.f / (1.f + expf(-go));
    float c = f_ * c0[idx] + i_ * g_;
    float h = o_ * tanhf(c);

    const int BR = Bq * Rq;
    out[idx] = h;
    if (out_size >= 2 * BR) out[BR + idx] = h;
    if (out_size >= 3 * BR) out[2 * BR + idx] = c;
}

// ---------------------------------------------------------------------------
extern "C" void kernel_launch(void* const* d_in, const int* in_sizes, int n_in,
                              void* d_out, int out_size)
{
    const float* xt     = (const float*)d_in[0];
    const float* attf   = (const float*)d_in[2];
    const float* h0     = (const float*)d_in[3];
    const float* c0     = (const float*)d_in[4];
    const float* Wctx   = (const float*)d_in[5];
    const float* bctx   = (const float*)d_in[6];
    const float* Wh2a   = (const float*)d_in[7];
    const float* bh2a   = (const float*)d_in[8];
    const float* Walpha = (const float*)d_in[9];
    const float* Wih    = (const float*)d_in[11];
    const float* Whh    = (const float*)d_in[12];
    float* out = (float*)d_out;

    void* p;
    cudaGetSymbolAddress(&p, g_att_h); float* atth = (float*)p;
    cudaGetSymbolAddress(&p, g_xcat);  float* xcat = (float*)p;
    cudaGetSymbolAddress(&p, g_Wcat);  float* wcat = (float*)p;
    cudaGetSymbolAddress(&p, g_gpart); float* gpart = (float*)p;

    cudaFuncSetAttribute(k_att_mma, cudaFuncAttributeMaxDynamicSharedMemorySize,
                         SMEM_MMA_BYTES);
    cudaFuncSetAttribute(k_gemm_tf32, cudaFuncAttributeMaxDynamicSharedMemorySize,
                         SMEM_MMA_BYTES);

    k_pack_w<<<2048, 256>>>(Wih, Whh);
    k_pack_x<<<(Bq * Iq + Bq * Rq) / 256, 256>>>(xt, h0);

    // att_h = h0 @ W_h2a^T + b_h2a   (tf32 mma; M=256,N=512,K=512)
    k_gemm_tf32<<<dim3(Hq / 128, Bq / 128, 1), 128, SMEM_MMA_BYTES>>>(
        h0, Rq, Wh2a, Rq, atth, Hq, bh2a, Rq, 0);

    // big fused GEMM (tf32 mma) -> score partials (4 n-tiles)
    k_att_mma<<<dim3(Hq / 128, MLq / 128), 128, SMEM_MMA_BYTES>>>(
        attf, Wctx, bctx, Walpha);

    k_softmax<<<Bq, 256>>>();

    k_attres<<<dim3(Aq / 256, Bq), 256>>>(attf);

    // gates = xcat @ Wcat^T   (tf32 mma; M=256,N=2048,K=3072, split-K=4)
    k_gemm_tf32<<<dim3(G4q / 128, Bq / 128, 4), 128, SMEM_MMA_BYTES>>>(
        xcat, KXq, wcat, KXq, gpart, G4q, nullptr, KXq / 4, Bq * G4q);

    k_lstm<<<(Bq * Rq) / 256, 256>>>(c0, out, out_size);
}